// round 1
// baseline (speedup 1.0000x reference)
#include <cuda_runtime.h>

#define NBATCH 32
#define NN 1024

// scratch: ranks[b, j]  (32 x 1024 floats = 128 KB)
__device__ float g_ranks[NBATCH * NN];

// ---------------------------------------------------------------------------
// Kernel 1: per batch row — bitonic sort (descending, with index payload),
// sequential PAV isotonic regression (thread 0), scatter ranks via inverse perm.
// One block per batch row, 1024 threads.
// ---------------------------------------------------------------------------
__global__ void __launch_bounds__(NN) sort_pav_kernel(const float* __restrict__ x) {
    __shared__ float  sv[NN];    // values: theta -> sorted s -> y = s - w
    __shared__ int    si[NN];    // permutation payload
    __shared__ float  sol[NN];   // isotonic solution (expanded)
    __shared__ double psum[NN];  // PAV stack: block sums
    __shared__ int    pcnt[NN];  // PAV stack: block counts

    const int b = blockIdx.x;
    const int t = threadIdx.x;

    sv[t] = x[b * NN + t];       // eps = 1.0 -> theta = x
    si[t] = t;
    __syncthreads();

    // Bitonic sort, final order DESCENDING (matches argsort(-theta))
    for (int k = 2; k <= NN; k <<= 1) {
        for (int j = k >> 1; j > 0; j >>= 1) {
            int ixj = t ^ j;
            if (ixj > t) {
                float a = sv[t], c = sv[ixj];
                bool desc = ((t & k) == 0);   // this segment sorts descending
                bool doswap = desc ? (a < c) : (a > c);
                if (doswap) {
                    sv[t] = c; sv[ixj] = a;
                    int tmp = si[t]; si[t] = si[ixj]; si[ixj] = tmp;
                }
            }
            __syncthreads();
        }
    }

    // y = s - w,  w[t] = NN - t  (i.e. [n, n-1, ..., 1])
    const float s_t = sv[t];
    sv[t] = s_t - (float)(NN - t);
    __syncthreads();

    // Sequential PAV (non-increasing isotonic regression) on y, thread 0.
    // Stack of finalized blocks in shared; rightmost block cached in registers.
    if (t == 0) {
        int    nb    = 0;
        double lastS = (double)sv[0];
        int    lastC = 1;
        for (int i = 1; i < NN; i++) {
            double cS = (double)sv[i];
            int    cC = 1;
            // merge while mean(last) < mean(cur)   (violates non-increasing)
            while (lastC > 0 && lastS * (double)cC < cS * (double)lastC) {
                cS += lastS; cC += lastC;
                if (nb == 0) { lastC = 0; break; }
                nb--;
                lastS = psum[nb]; lastC = pcnt[nb];
            }
            if (lastC > 0) { psum[nb] = lastS; pcnt[nb] = lastC; nb++; }
            lastS = cS; lastC = cC;
        }
        psum[nb] = lastS; pcnt[nb] = lastC; nb++;

        // expand block means into sol[]
        int pos = 0;
        for (int bi = 0; bi < nb; bi++) {
            float m = (float)(psum[bi] / (double)pcnt[bi]);
            int   c = pcnt[bi];
            for (int q = 0; q < c; q++) sol[pos++] = m;
        }
    }
    __syncthreads();

    // primal = s - sol ; scatter back through the permutation
    float primal = s_t - sol[t];
    g_ranks[b * NN + si[t]] = primal;
}

// ---------------------------------------------------------------------------
// Kernel 2: out[b, j, i] = relu(1 - |ranks[b,j] - (i+1)|), float4 per thread.
// 32*1024*1024 floats = 8M float4 -> 8M threads. Pure streaming store.
// ---------------------------------------------------------------------------
__global__ void __launch_bounds__(256) expand_kernel(float4* __restrict__ out) {
    const int tid = blockIdx.x * blockDim.x + threadIdx.x;   // 0 .. 8M-1
    const int row = tid >> 8;          // 256 float4-threads per (b,j) row
    const int i0  = (tid & 255) << 2;  // starting i within row
    const float r = g_ranks[row];      // broadcast, L1-resident

    float4 v;
    v.x = fmaxf(0.0f, 1.0f - fabsf(r - (float)(i0 + 1)));
    v.y = fmaxf(0.0f, 1.0f - fabsf(r - (float)(i0 + 2)));
    v.z = fmaxf(0.0f, 1.0f - fabsf(r - (float)(i0 + 3)));
    v.w = fmaxf(0.0f, 1.0f - fabsf(r - (float)(i0 + 4)));
    out[tid] = v;
}

extern "C" void kernel_launch(void* const* d_in, const int* in_sizes, int n_in,
                              void* d_out, int out_size) {
    const float* x = (const float*)d_in[0];
    sort_pav_kernel<<<NBATCH, NN>>>(x);

    const int total4 = NBATCH * NN * NN / 4;   // 8,388,608
    expand_kernel<<<total4 / 256, 256>>>((float4*)d_out);
}

// round 2
// speedup vs baseline: 5.7162x; 5.7162x over previous
#include <cuda_runtime.h>

#define NBATCH 32
#define NN 1024

// scratch: ranks[b, j]  (32 x 1024 floats = 128 KB)
__device__ float g_ranks[NBATCH * NN];

// ---------------------------------------------------------------------------
// Kernel 1: per batch row:
//   hybrid bitonic sort (registers + shfl for stride<32, shared for >=32),
//   warp-parallel chunked PAV + short serial merge, binary-search expansion,
//   scatter ranks through inverse permutation.
// One block of 1024 threads per batch row.
// ---------------------------------------------------------------------------
__global__ void __launch_bounds__(NN) sort_pav_kernel(const float* __restrict__ x) {
    __shared__ float sv[NN];       // exchange buffer / y values
    __shared__ int   si[NN];       // exchange buffer for ids
    __shared__ float cm[NN];       // chunk PAV stacks: means (lane l -> [32l, 32l+32))
    __shared__ int   cc[NN];       // chunk PAV stacks: counts
    __shared__ int   bn[32];       // blocks per chunk
    __shared__ float fm[NN];       // final block means
    __shared__ int   fc[NN];       // final block counts
    __shared__ int   fs[NN + 1];   // final block start offsets
    __shared__ int   nbF_s;

    const int b = blockIdx.x;
    const int t = threadIdx.x;

    float v  = x[b * NN + t];      // eps = 1.0 -> theta = x
    int   id = t;

    // ---- bitonic sort, final order DESCENDING, tie-broken by id ----
    for (int k = 2; k <= NN; k <<= 1) {
        const bool desc = ((t & k) == 0);
        // strides >= 32: via shared memory
        for (int j = k >> 1; j >= 32; j >>= 1) {
            sv[t] = v; si[t] = id;
            __syncthreads();
            float ov  = sv[t ^ j];
            int   oid = si[t ^ j];
            bool up = (t & j) != 0;
            bool og = (ov > v) || (ov == v && oid > id);   // strict total order
            if (og == (desc != up)) { v = ov; id = oid; }
            __syncthreads();
        }
        // strides < 32: via warp shuffle
        int j0 = (k >> 1) < 16 ? (k >> 1) : 16;
        for (int j = j0; j >= 1; j >>= 1) {
            float ov  = __shfl_xor_sync(0xFFFFFFFFu, v, j);
            int   oid = __shfl_xor_sync(0xFFFFFFFFu, id, j);
            bool up = (t & j) != 0;
            bool og = (ov > v) || (ov == v && oid > id);
            if (og == (desc != up)) { v = ov; id = oid; }
        }
    }

    // y = s - w,  w[t] = NN - t
    const float s_t = v;
    sv[t] = s_t - (float)(NN - t);
    __syncthreads();

    // ---- chunked PAV: warp 0, lane l handles y[32l .. 32l+31] ----
    if (t < 32) {
        const int base = t * 32;
        int   nb = 0;                 // entries below top
        float tm = sv[base];          // top block mean
        int   tc = 1;                 // top block count
        for (int i = 1; i < 32; i++) {
            float m = sv[base + i];
            int   c = 1;
            while (tc > 0 && tm < m) {          // violates non-increasing -> merge
                m = (tm * (float)tc + m * (float)c) / (float)(tc + c);
                c += tc;
                if (nb == 0) { tc = 0; break; }
                nb--; tm = cm[base + nb]; tc = cc[base + nb];
            }
            if (tc > 0) { cm[base + nb] = tm; cc[base + nb] = tc; nb++; }
            tm = m; tc = c;
        }
        cm[base + nb] = tm; cc[base + nb] = tc; nb++;
        bn[t] = nb;
    }
    __syncthreads();

    // ---- serial merge of chunk stacks (expected ~32-64 cheap iterations) ----
    if (t == 0) {
        int   nb = 0;
        float tm = 0.0f;
        int   tc = 0;
        for (int l = 0; l < 32; l++) {
            const int cnt  = bn[l];
            const int base = l * 32;
            for (int i = 0; i < cnt; i++) {
                float m = cm[base + i];
                int   c = cc[base + i];
                if (tc == 0) { tm = m; tc = c; continue; }
                while (tc > 0 && tm < m) {
                    m = (tm * (float)tc + m * (float)c) / (float)(tc + c);
                    c += tc;
                    if (nb == 0) { tc = 0; break; }
                    nb--; tm = fm[nb]; tc = fc[nb];
                }
                if (tc > 0) { fm[nb] = tm; fc[nb] = tc; nb++; }
                tm = m; tc = c;
            }
        }
        fm[nb] = tm; fc[nb] = tc; nb++;
        int pos = 0;
        for (int q = 0; q < nb; q++) { fs[q] = pos; pos += fc[q]; }
        fs[nb] = pos;
        nbF_s = nb;
    }
    __syncthreads();

    // ---- expand sol via binary search over block starts ----
    {
        int lo = 0, hi = nbF_s - 1;
        while (lo < hi) {
            int mid = (lo + hi + 1) >> 1;
            if (fs[mid] <= t) lo = mid; else hi = mid - 1;
        }
        float sol = fm[lo];
        // primal = s - sol ; scatter through permutation
        g_ranks[b * NN + id] = s_t - sol;
    }
}

// ---------------------------------------------------------------------------
// Kernel 2: out[b, j, i] = relu(1 - |ranks[b,j] - (i+1)|), float4 per thread.
// Pure streaming store, near DRAM-write roofline.
// ---------------------------------------------------------------------------
__global__ void __launch_bounds__(256) expand_kernel(float4* __restrict__ out) {
    const int tid = blockIdx.x * blockDim.x + threadIdx.x;   // 0 .. 8M-1
    const int row = tid >> 8;          // 256 float4-threads per (b,j) row
    const int i0  = (tid & 255) << 2;  // starting i within row
    const float r = g_ranks[row];      // broadcast, L1-resident

    float4 v;
    v.x = fmaxf(0.0f, 1.0f - fabsf(r - (float)(i0 + 1)));
    v.y = fmaxf(0.0f, 1.0f - fabsf(r - (float)(i0 + 2)));
    v.z = fmaxf(0.0f, 1.0f - fabsf(r - (float)(i0 + 3)));
    v.w = fmaxf(0.0f, 1.0f - fabsf(r - (float)(i0 + 4)));
    out[tid] = v;
}

extern "C" void kernel_launch(void* const* d_in, const int* in_sizes, int n_in,
                              void* d_out, int out_size) {
    const float* x = (const float*)d_in[0];
    sort_pav_kernel<<<NBATCH, NN>>>(x);

    const int total4 = NBATCH * NN * NN / 4;   // 8,388,608
    expand_kernel<<<total4 / 256, 256>>>((float4*)d_out);
}